// round 16
// baseline (speedup 1.0000x reference)
#include <cuda_runtime.h>
#include <math_constants.h>

#define BB   32
#define NP   1024
#define KNN  20
#define NPTS (BB*NP)
#define NEDGE (NPTS*KNN)
#define QB    (BB/4)          // 8 batches per chunk
#define QPTS  (NPTS/4)        // 8192 points per chunk
#define QEDGE (NEDGE/4)       // 163840 edges per chunk

// ---------------- scratch (device globals; no allocation allowed) ----------
__device__ float g_D[(size_t)BB*NP*NP];
__device__ int   g_idx[NPTS*KNN];
__device__ float g_p1[NPTS*64];
__device__ float g_q1[NPTS*64];
__device__ float g_f1[NPTS*64];
__device__ float g_norm[NPTS];
__device__ float g_p2[NPTS*128];
__device__ float g_q2[NPTS*128];
__device__ float g_f2[NPTS*128];
__device__ float g_pool[BB*512];

// monotonic u32 key for finite floats (never -0.0 here)
__device__ __forceinline__ unsigned monokey(float f) {
    unsigned u = __float_as_uint(f);
    return (u & 0x80000000u) ? ~u : (u | 0x80000000u);
}

// ---------------- 1) fused kNN on xyz: REDUX + top-2 cached selection ------
__global__ void __launch_bounds__(256) knn3_kernel(const float* __restrict__ x, int rb0) {
    __shared__ float sx[NP], sy[NP], sz[NP], sq[NP];
    int rowBase = rb0 + blockIdx.x * 8;
    int b = rowBase >> 10;
    const float* xb = x + (size_t)b * NP * 3;
    for (int i = threadIdx.x; i < NP; i += 256) {
        float a0 = xb[i*3], a1 = xb[i*3+1], a2 = xb[i*3+2];
        sx[i] = a0; sy[i] = a1; sz[i] = a2;
        sq[i] = a0*a0 + a1*a1 + a2*a2;
    }
    __syncthreads();
    int warp = threadIdx.x >> 5, lane = threadIdx.x & 31;
    int n  = rowBase + warp;
    int nl = n & (NP - 1);
    float qx = sx[nl], qy = sy[nl], qz = sz[nl], qs = sq[nl];
    float v[32];
#pragma unroll
    for (int i = 0; i < 32; i++) {
        int m = lane + (i << 5);
        float d = qs + sq[m] - 2.0f * (qx*sx[m] + qy*sy[m] + qz*sz[m]);
        v[i] = (m == nl) ? CUDART_INF_F : d;
    }
    float bv = v[0]; int bi = 0;
    float bv2 = CUDART_INF_F; int bi2 = -1;
#pragma unroll
    for (int i = 1; i < 32; i++) {
        float vi = v[i];
        if (vi < bv)       { bv2 = bv; bi2 = bi; bv = vi; bi = i; }
        else if (vi < bv2) { bv2 = vi; bi2 = i; }
    }
    unsigned popped = 0u;
    for (int r = 0; r < KNN; r++) {
        unsigned key = monokey(bv);
        unsigned rm  = __reduce_min_sync(0xffffffffu, key);
        unsigned myg = (unsigned)((bi << 5) | lane);
        unsigned cand = (key == rm) ? myg : 0xffffffffu;
        unsigned mi = __reduce_min_sync(0xffffffffu, cand);
        if (lane == 0) g_idx[n * KNN + r] = (int)mi;
        if (mi == myg) {
            popped |= 1u << bi;
            if (bi2 >= 0) { bv = bv2; bi = bi2; bi2 = -1; }
            else {
                bv = CUDART_INF_F; bi = 0; bv2 = CUDART_INF_F; bi2 = -1;
#pragma unroll
                for (int i = 0; i < 32; i++) {
                    if (popped & (1u << i)) continue;
                    float vi = v[i];
                    if (vi < bv)       { bv2 = bv; bi2 = bi; bv = vi; bi = i; }
                    else if (vi < bv2) { bv2 = vi; bi2 = i; }
                }
            }
        }
    }
}

// ---------------- 2) top-20 per row of g_D: same selection, float4 loads ----
__global__ void topk_kernel(int rb0) {
    int row  = rb0 + blockIdx.x * 8 + (threadIdx.x >> 5);
    int lane = threadIdx.x & 31;
    int nl = row & (NP - 1);
    const float* d = g_D + (size_t)row * NP;
    float v[32];
#pragma unroll
    for (int g = 0; g < 8; g++) {
        int base = g * 128 + lane * 4;
        float4 t4 = *(const float4*)(d + base);
        v[g*4+0] = (base + 0 == nl) ? CUDART_INF_F : t4.x;
        v[g*4+1] = (base + 1 == nl) ? CUDART_INF_F : t4.y;
        v[g*4+2] = (base + 2 == nl) ? CUDART_INF_F : t4.z;
        v[g*4+3] = (base + 3 == nl) ? CUDART_INF_F : t4.w;
    }
    float bv = v[0]; int bi = 0;
    float bv2 = CUDART_INF_F; int bi2 = -1;
#pragma unroll
    for (int i = 1; i < 32; i++) {
        float vi = v[i];
        if (vi < bv)       { bv2 = bv; bi2 = bi; bv = vi; bi = i; }
        else if (vi < bv2) { bv2 = vi; bi2 = i; }
    }
    unsigned popped = 0u;
    for (int r = 0; r < KNN; r++) {
        unsigned key = monokey(bv);
        unsigned rm  = __reduce_min_sync(0xffffffffu, key);
        unsigned myg = (unsigned)(((bi >> 2) << 7) | (lane << 2) | (bi & 3));
        unsigned cand = (key == rm) ? myg : 0xffffffffu;
        unsigned mi = __reduce_min_sync(0xffffffffu, cand);
        if (lane == 0) g_idx[row * KNN + r] = (int)mi;
        if (mi == myg) {
            popped |= 1u << bi;
            if (bi2 >= 0) { bv = bv2; bi = bi2; bi2 = -1; }
            else {
                bv = CUDART_INF_F; bi = 0; bv2 = CUDART_INF_F; bi2 = -1;
#pragma unroll
                for (int i = 0; i < 32; i++) {
                    if (popped & (1u << i)) continue;
                    float vi = v[i];
                    if (vi < bv)       { bv2 = bv; bi2 = bi; bv = vi; bi = i; }
                    else if (vi < bv2) { bv2 = vi; bi2 = i; }
                }
            }
        }
    }
}

// ---------------- 3) EdgeConv1 layer-1 split precompute (+ zero f1) --------
__global__ void pre1_kernel(const float* __restrict__ x,
                            const float* __restrict__ W1,
                            const float* __restrict__ b1) {
    int id = blockIdx.x * blockDim.x + threadIdx.x;
    if (id >= NPTS * 64) return;
    int n = id >> 6, t = id & 63;
    float x0 = x[n*3], x1 = x[n*3+1], x2 = x[n*3+2];
    float wa0 = W1[t],       wa1 = W1[64 + t],  wa2 = W1[128 + t];
    float wb0 = W1[192 + t], wb1 = W1[256 + t], wb2 = W1[320 + t];
    float q = x0*wb0 + x1*wb1 + x2*wb2;
    float p = b1[t] + x0*(wa0-wb0) + x1*(wa1-wb1) + x2*(wa2-wb2);
    g_p1[id] = p;
    g_q1[id] = q;
    g_f1[id] = 0.0f;
}

// ---------------- 4) EdgeConv1 fused 2-layer GEMM (edge-base offset) --------
#define ETP 260
#define EC1_SMEM ((64*ETP + 4096 + 4096 + 64 + 64) * 4)
__global__ void __launch_bounds__(256, 2) ec1_kernel(const float* __restrict__ W2,
                                                     const float* __restrict__ b2,
                                                     const float* __restrict__ W3,
                                                     const float* __restrict__ b3,
                                                     int eb0) {
    extern __shared__ float sm[];
    float* ET  = sm;
    float* sW2 = sm + 64*ETP;
    float* sW3 = sW2 + 4096;
    float* sB2 = sW3 + 4096;
    float* sB3 = sB2 + 64;
    int tid = threadIdx.x;
    int tx = tid & 7, ty = tid >> 3;

    for (int i = tid; i < 4096; i += 256) { sW2[i] = W2[i]; sW3[i] = W3[i]; }
    if (tid < 64) { sB2[tid] = b2[tid]; sB3[tid] = b3[tid]; }

    int B0 = eb0 + blockIdx.x * 256;
    int g  = B0 + tid;
    int p  = g / KNN;
    int b  = p >> 10;
    int j  = g_idx[g];
    const float* pr = g_p1 + (size_t)p * 64;
    const float* qr = g_q1 + ((size_t)(b << 10) + j) * 64;
    __syncthreads();
#pragma unroll
    for (int c = 0; c < 64; c += 4) {
        float4 pv = *(const float4*)(pr + c);
        float4 qv = *(const float4*)(qr + c);
        ET[(c+0)*ETP + tid] = fmaxf(pv.x + qv.x, 0.0f);
        ET[(c+1)*ETP + tid] = fmaxf(pv.y + qv.y, 0.0f);
        ET[(c+2)*ETP + tid] = fmaxf(pv.z + qv.z, 0.0f);
        ET[(c+3)*ETP + tid] = fmaxf(pv.w + qv.w, 0.0f);
    }
    __syncthreads();

    float acc[8][8];
#pragma unroll
    for (int i = 0; i < 8; i++)
#pragma unroll
        for (int jj = 0; jj < 8; jj++) acc[i][jj] = 0.0f;
#pragma unroll 4
    for (int k = 0; k < 64; k++) {
        float4 a0 = *(const float4*)(ET + k*ETP + ty*8);
        float4 a1 = *(const float4*)(ET + k*ETP + ty*8 + 4);
        float4 w0 = *(const float4*)(sW2 + k*64 + tx*8);
        float4 w1 = *(const float4*)(sW2 + k*64 + tx*8 + 4);
        float a[8] = {a0.x,a0.y,a0.z,a0.w,a1.x,a1.y,a1.z,a1.w};
        float w[8] = {w0.x,w0.y,w0.z,w0.w,w1.x,w1.y,w1.z,w1.w};
#pragma unroll
        for (int i = 0; i < 8; i++)
#pragma unroll
            for (int jj = 0; jj < 8; jj++) acc[i][jj] = fmaf(a[i], w[jj], acc[i][jj]);
    }
    float bv2[8], bv3[8];
#pragma unroll
    for (int jj = 0; jj < 8; jj++) { bv2[jj] = sB2[tx*8+jj]; bv3[jj] = sB3[tx*8+jj]; }
    __syncthreads();
#pragma unroll
    for (int jj = 0; jj < 8; jj++)
#pragma unroll
        for (int i = 0; i < 8; i++)
            ET[(tx*8+jj)*ETP + ty*8 + i] = fmaxf(acc[i][jj] + bv2[jj], 0.0f);
    __syncthreads();

#pragma unroll
    for (int i = 0; i < 8; i++)
#pragma unroll
        for (int jj = 0; jj < 8; jj++) acc[i][jj] = 0.0f;
#pragma unroll 4
    for (int k = 0; k < 64; k++) {
        float4 a0 = *(const float4*)(ET + k*ETP + ty*8);
        float4 a1 = *(const float4*)(ET + k*ETP + ty*8 + 4);
        float4 w0 = *(const float4*)(sW3 + k*64 + tx*8);
        float4 w1 = *(const float4*)(sW3 + k*64 + tx*8 + 4);
        float a[8] = {a0.x,a0.y,a0.z,a0.w,a1.x,a1.y,a1.z,a1.w};
        float w[8] = {w0.x,w0.y,w0.z,w0.w,w1.x,w1.y,w1.z,w1.w};
#pragma unroll
        for (int i = 0; i < 8; i++)
#pragma unroll
            for (int jj = 0; jj < 8; jj++) acc[i][jj] = fmaf(a[i], w[jj], acc[i][jj]);
    }
    __syncthreads();
#pragma unroll
    for (int i = 0; i < 8; i++) {
        float4 v0, v1;
        v0.x = acc[i][0] + bv3[0]; v0.y = acc[i][1] + bv3[1];
        v0.z = acc[i][2] + bv3[2]; v0.w = acc[i][3] + bv3[3];
        v1.x = acc[i][4] + bv3[4]; v1.y = acc[i][5] + bv3[5];
        v1.z = acc[i][6] + bv3[6]; v1.w = acc[i][7] + bv3[7];
        *(float4*)(ET + (ty*8+i)*64 + tx*8)     = v0;
        *(float4*)(ET + (ty*8+i)*64 + tx*8 + 4) = v1;
    }
    __syncthreads();

    int pFirst = B0 / KNN;
    int pLast  = (B0 + 255) / KNN;
    int nseg   = pLast - pFirst + 1;
    int ch = tid & 63;
    for (int s = tid >> 6; s < nseg; s += 4) {
        int pt = pFirst + s;
        int r0 = max(pt * KNN,       B0) - B0;
        int r1 = min(pt * KNN + KNN, B0 + 256) - B0;
        if (r0 >= r1) continue;
        float m = ET[r0*64 + ch];
        for (int r = r0 + 1; r < r1; r++) m = fmaxf(m, ET[r*64 + ch]);
        atomicMax((int*)&g_f1[(size_t)pt*64 + ch], __float_as_int(m));
    }
}

// ---------------- 4b) squared norms of f1 rows (point offset) ---------------
__global__ void norm64_kernel(int nb0) {
    int n = nb0 + blockIdx.x * 256 + threadIdx.x;
    const float4* r = (const float4*)(g_f1 + (size_t)n * 64);
    float s = 0.0f;
#pragma unroll
    for (int i = 0; i < 16; i++) {
        float4 v = r[i];
        s += v.x*v.x + v.y*v.y + v.z*v.z + v.w*v.w;
    }
    g_norm[n] = s;
}

// ---------------- 5) dist64: SYMMETRIC Gram GEMM (batch offset) -------------
#define TS 132
#define D64_SMEM ((32*TS*2 + 256) * 4)
__global__ void __launch_bounds__(256) dist64_kernel(int bb0) {
    extern __shared__ float sm[];
    float* sAt = sm;
    float* sBt = sm + 32*TS;
    float* snA = sm + 64*TS;
    float* snB = snA + 128;
    int b = bb0 + blockIdx.y;
    int t = blockIdx.x, ti = 0;
    while (t >= 8 - ti) { t -= 8 - ti; ti++; }
    int tj = ti + t;
    int m0 = ti * 128, n0 = tj * 128;
    int tid = threadIdx.x;
    int tx = tid & 15, ty = tid >> 4;
    const float* F = g_f1 + (size_t)b * NP * 64;

    if (tid < 128)      snA[tid]       = g_norm[b*NP + m0 + tid];
    else                snB[tid - 128] = g_norm[b*NP + n0 + tid - 128];

    float acc[8][8];
#pragma unroll
    for (int i = 0; i < 8; i++)
#pragma unroll
        for (int j = 0; j < 8; j++) acc[i][j] = 0.0f;

    for (int kc = 0; kc < 2; kc++) {
        __syncthreads();
#pragma unroll
        for (int l = 0; l < 16; l++) {
            int idx = l * 256 + tid;
            int r = idx >> 5, c = idx & 31;
            sAt[c * TS + r] = F[(size_t)(m0 + r) * 64 + kc * 32 + c];
            sBt[c * TS + r] = F[(size_t)(n0 + r) * 64 + kc * 32 + c];
        }
        __syncthreads();
        for (int k = 0; k < 32; k++) {
            float4 a0 = *(const float4*)(sAt + k * TS + ty * 8);
            float4 a1 = *(const float4*)(sAt + k * TS + ty * 8 + 4);
            float4 c0 = *(const float4*)(sBt + k * TS + tx * 4);
            float4 c1 = *(const float4*)(sBt + k * TS + 64 + tx * 4);
            float a[8]  = {a0.x, a0.y, a0.z, a0.w, a1.x, a1.y, a1.z, a1.w};
            float bv[8] = {c0.x, c0.y, c0.z, c0.w, c1.x, c1.y, c1.z, c1.w};
#pragma unroll
            for (int i = 0; i < 8; i++)
#pragma unroll
                for (int j = 0; j < 8; j++) acc[i][j] = fmaf(a[i], bv[j], acc[i][j]);
        }
    }
    float* Dp = g_D + (size_t)b * NP * NP;
    float nb_[8];
#pragma unroll
    for (int j = 0; j < 8; j++) nb_[j] = (j < 4) ? snB[tx*4 + j] : snB[64 + tx*4 + (j-4)];

    float dv[8][8];
#pragma unroll
    for (int i = 0; i < 8; i++) {
        float nai = snA[ty*8 + i];
#pragma unroll
        for (int j = 0; j < 8; j++) dv[i][j] = nai + nb_[j] - 2.0f * acc[i][j];
    }
#pragma unroll
    for (int i = 0; i < 8; i++) {
        float* row = Dp + (size_t)(m0 + ty*8 + i) * NP;
        *(float4*)(row + n0 + tx*4)      = make_float4(dv[i][0], dv[i][1], dv[i][2], dv[i][3]);
        *(float4*)(row + n0 + 64 + tx*4) = make_float4(dv[i][4], dv[i][5], dv[i][6], dv[i][7]);
    }
    if (ti != tj) {
#pragma unroll
        for (int j = 0; j < 8; j++) {
            int cl = (j < 4) ? (tx*4 + j) : (64 + tx*4 + (j-4));
            float* row = Dp + (size_t)(n0 + cl) * NP + m0 + ty*8;
            *(float4*)row       = make_float4(dv[0][j], dv[1][j], dv[2][j], dv[3][j]);
            *(float4*)(row + 4) = make_float4(dv[4][j], dv[5][j], dv[6][j], dv[7][j]);
        }
    }
}

// ---------------- 6) pre2 as GEMM (m-tile offset) ---------------------------
#define PRE2_SMEM ((32*TS*2 + 128) * 4)
__global__ void __launch_bounds__(256) pre2_kernel(const float* __restrict__ W4,
                                                   const float* __restrict__ b4,
                                                   int mt0) {
    extern __shared__ float sm[];
    float* sAt = sm;
    float* sBt = sm + 32*TS;
    float* sBias = sm + 64*TS;
    int nblk = blockIdx.x;
    int m0 = (mt0 + blockIdx.y) * 128;
    int tid = threadIdx.x;
    int tx = tid & 15, ty = tid >> 4;

    if (tid < 128) sBias[tid] = (nblk == 0) ? b4[tid] : 0.0f;

    float acc[8][8];
#pragma unroll
    for (int i = 0; i < 8; i++)
#pragma unroll
        for (int j = 0; j < 8; j++) acc[i][j] = 0.0f;

    for (int kc = 0; kc < 2; kc++) {
        __syncthreads();
#pragma unroll
        for (int l = 0; l < 16; l++) {
            int idx = l * 256 + tid;
            int r = idx >> 5, c = idx & 31;
            sAt[c * TS + r] = g_f1[(size_t)(m0 + r) * 64 + kc * 32 + c];
        }
#pragma unroll
        for (int l = 0; l < 16; l++) {
            int idx = l * 256 + tid;
            int nl = idx & 127, kk = idx >> 7;
            int k = kc * 32 + kk;
            float wb = W4[(64 + k) * 128 + nl];
            float w  = (nblk == 0) ? (W4[k * 128 + nl] - wb) : wb;
            sBt[kk * TS + nl] = w;
        }
        __syncthreads();
        for (int k = 0; k < 32; k++) {
            float4 a0 = *(const float4*)(sAt + k * TS + ty * 8);
            float4 a1 = *(const float4*)(sAt + k * TS + ty * 8 + 4);
            float4 c0 = *(const float4*)(sBt + k * TS + tx * 8);
            float4 c1 = *(const float4*)(sBt + k * TS + tx * 8 + 4);
            float a[8]  = {a0.x, a0.y, a0.z, a0.w, a1.x, a1.y, a1.z, a1.w};
            float bv[8] = {c0.x, c0.y, c0.z, c0.w, c1.x, c1.y, c1.z, c1.w};
#pragma unroll
            for (int i = 0; i < 8; i++)
#pragma unroll
                for (int j = 0; j < 8; j++) acc[i][j] = fmaf(a[i], bv[j], acc[i][j]);
        }
    }
    float* dst = (nblk == 0) ? g_p2 : g_q2;
    float bb[8];
#pragma unroll
    for (int j = 0; j < 8; j++) bb[j] = sBias[tx*8 + j];
#pragma unroll
    for (int i = 0; i < 8; i++) {
        float4 o0, o1;
        o0.x = acc[i][0] + bb[0]; o0.y = acc[i][1] + bb[1];
        o0.z = acc[i][2] + bb[2]; o0.w = acc[i][3] + bb[3];
        o1.x = acc[i][4] + bb[4]; o1.y = acc[i][5] + bb[5];
        o1.z = acc[i][6] + bb[6]; o1.w = acc[i][7] + bb[7];
        float* row = dst + (size_t)(m0 + ty*8 + i) * 128 + tx*8;
        *(float4*)row       = o0;
        *(float4*)(row + 4) = o1;
    }
}

// ---------------- 7) EdgeConv2: max_k relu(p + q) (point offset) ------------
__global__ void ec2_kernel(int nb0) {
    int n = nb0 + blockIdx.x, t = threadIdx.x;
    int b = n >> 10;
    float p = g_p2[(size_t)n * 128 + t];
    const int* idxp = g_idx + n * KNN;
    float best = 0.0f;
#pragma unroll
    for (int k = 0; k < KNN; k++) {
        int j = idxp[k];
        float q = g_q2[((size_t)(b << 10) + j) * 128 + t];
        best = fmaxf(best, p + q);
    }
    g_f2[(size_t)n * 128 + t] = best;
}

// ---------------- 8) pool: 128x256 tiles (m-tile offset) --------------------
__global__ void zero_pool_kernel() {
    int i = blockIdx.x * blockDim.x + threadIdx.x;
    if (i < BB * 512) g_pool[i] = 0.0f;
}

#define POOLN 260
#define POOL_SMEM ((32*TS + 32*POOLN + 16*256) * 4)
__global__ void __launch_bounds__(512) pool_kernel(const float* __restrict__ Wp,
                                                   const float* __restrict__ bp,
                                                   int mt0) {
    extern __shared__ float smp[];
    float* sAt  = smp;
    float* sBt  = smp + 32*TS;
    float* sred = smp + 32*TS + 32*POOLN;
    int m0 = (mt0 + blockIdx.x) * 128, n0 = blockIdx.y * 256;
    int b  = m0 >> 10;
    int tid = threadIdx.x;
    int tx = tid & 31, ty = tid >> 5;

    float acc[8][8];
#pragma unroll
    for (int i = 0; i < 8; i++)
#pragma unroll
        for (int j = 0; j < 8; j++) acc[i][j] = 0.0f;

    for (int kc = 0; kc < 4; kc++) {
        __syncthreads();
#pragma unroll
        for (int l = 0; l < 8; l++) {
            int idx = l * 512 + tid;
            int r = idx >> 5, c = idx & 31;
            sAt[c * TS + r] = g_f2[(size_t)(m0 + r) * 128 + kc * 32 + c];
        }
#pragma unroll
        for (int l = 0; l < 16; l++) {
            int idx = l * 512 + tid;
            int nn = idx & 255, kk = idx >> 8;
            sBt[kk * POOLN + nn] = Wp[(size_t)(kc * 32 + kk) * 512 + n0 + nn];
        }
        __syncthreads();
        for (int k = 0; k < 32; k++) {
            float4 a0 = *(const float4*)(sAt + k * TS + ty * 8);
            float4 a1 = *(const float4*)(sAt + k * TS + ty * 8 + 4);
            float4 c0 = *(const float4*)(sBt + k * POOLN + tx * 8);
            float4 c1 = *(const float4*)(sBt + k * POOLN + tx * 8 + 4);
            float a[8]  = {a0.x, a0.y, a0.z, a0.w, a1.x, a1.y, a1.z, a1.w};
            float bv[8] = {c0.x, c0.y, c0.z, c0.w, c1.x, c1.y, c1.z, c1.w};
#pragma unroll
            for (int i = 0; i < 8; i++)
#pragma unroll
                for (int j = 0; j < 8; j++) acc[i][j] = fmaf(a[i], bv[j], acc[i][j]);
        }
    }
#pragma unroll
    for (int j = 0; j < 8; j++) {
        int col = n0 + tx * 8 + j;
        float bpv = bp[col];
        float cm = 0.0f;
#pragma unroll
        for (int i = 0; i < 8; i++) cm = fmaxf(cm, acc[i][j] + bpv);
        sred[ty * 256 + tx * 8 + j] = cm;
    }
    __syncthreads();
    if (ty == 0) {
#pragma unroll
        for (int j = 0; j < 8; j++) {
            int c = tx * 8 + j;
            float cm = 0.0f;
#pragma unroll
            for (int yy = 0; yy < 16; yy++) cm = fmaxf(cm, sred[yy * 256 + c]);
            atomicMax((int*)&g_pool[b * 512 + n0 + c], __float_as_int(cm));
        }
    }
}

// ---------------- 9) classifier head ----------------------------------------
__global__ void head_kernel(const float* __restrict__ Wt1, const float* __restrict__ bt1,
                            const float* __restrict__ Wt2, const float* __restrict__ bt2,
                            float* __restrict__ out) {
    __shared__ float sp[512];
    __shared__ float st[256];
    int b = blockIdx.x, t = threadIdx.x;
    sp[t]       = g_pool[b * 512 + t];
    sp[256 + t] = g_pool[b * 512 + 256 + t];
    __syncthreads();
    float acc = bt1[t];
#pragma unroll 8
    for (int c = 0; c < 512; c++) acc = fmaf(sp[c], Wt1[c * 256 + t], acc);
    st[t] = fmaxf(acc, 0.0f);
    __syncthreads();
    if (t < 40) {
        float a2 = bt2[t];
#pragma unroll 8
        for (int c = 0; c < 256; c++) a2 = fmaf(st[c], Wt2[c * 40 + t], a2);
        out[b * 40 + t] = a2;
    }
}

// ---------------- launch: 4-chunk pipeline over 3 streams -------------------
extern "C" void kernel_launch(void* const* d_in, const int* in_sizes, int n_in,
                              void* d_out, int out_size) {
    const float* x   = (const float*)d_in[0];
    const float* W1  = (const float*)d_in[2];
    const float* b1  = (const float*)d_in[3];
    const float* W2  = (const float*)d_in[4];
    const float* b2  = (const float*)d_in[5];
    const float* W3  = (const float*)d_in[6];
    const float* b3  = (const float*)d_in[7];
    const float* W4  = (const float*)d_in[8];
    const float* b4  = (const float*)d_in[9];
    const float* Wp  = (const float*)d_in[10];
    const float* bp  = (const float*)d_in[11];
    const float* Wt1 = (const float*)d_in[12];
    const float* bt1 = (const float*)d_in[13];
    const float* Wt2 = (const float*)d_in[14];
    const float* bt2 = (const float*)d_in[15];
    float* out = (float*)d_out;

    static cudaStream_t s1 = nullptr, s2 = nullptr;
    static cudaEvent_t eR = nullptr, eP1 = nullptr, eZ = nullptr,
                       eK1 = nullptr, eK2 = nullptr, eK3 = nullptr,
                       eE0 = nullptr, eE1 = nullptr, eE2 = nullptr,
                       eT01 = nullptr, eT2 = nullptr;
    if (s1 == nullptr) {
        cudaStreamCreateWithFlags(&s1, cudaStreamNonBlocking);
        cudaStreamCreateWithFlags(&s2, cudaStreamNonBlocking);
        cudaEventCreateWithFlags(&eR,   cudaEventDisableTiming);
        cudaEventCreateWithFlags(&eP1,  cudaEventDisableTiming);
        cudaEventCreateWithFlags(&eZ,   cudaEventDisableTiming);
        cudaEventCreateWithFlags(&eK1,  cudaEventDisableTiming);
        cudaEventCreateWithFlags(&eK2,  cudaEventDisableTiming);
        cudaEventCreateWithFlags(&eK3,  cudaEventDisableTiming);
        cudaEventCreateWithFlags(&eE0,  cudaEventDisableTiming);
        cudaEventCreateWithFlags(&eE1,  cudaEventDisableTiming);
        cudaEventCreateWithFlags(&eE2,  cudaEventDisableTiming);
        cudaEventCreateWithFlags(&eT01, cudaEventDisableTiming);
        cudaEventCreateWithFlags(&eT2,  cudaEventDisableTiming);
        cudaFuncSetAttribute(ec1_kernel,    cudaFuncAttributeMaxDynamicSharedMemorySize, EC1_SMEM);
        cudaFuncSetAttribute(dist64_kernel, cudaFuncAttributeMaxDynamicSharedMemorySize, D64_SMEM);
        cudaFuncSetAttribute(pre2_kernel,   cudaFuncAttributeMaxDynamicSharedMemorySize, PRE2_SMEM);
        cudaFuncSetAttribute(pool_kernel,   cudaFuncAttributeMaxDynamicSharedMemorySize, POOL_SMEM);
    }

    cudaEventRecord(eR, 0);
    cudaStreamWaitEvent(s1, eR, 0);
    cudaStreamWaitEvent(s2, eR, 0);

    // s2: zero pool; kNN chunks 2,3
    zero_pool_kernel<<<16, 1024, 0, s2>>>();
    cudaEventRecord(eZ, s2);
    knn3_kernel<<<QPTS / 8, 256, 0, s2>>>(x, 2*QPTS);
    cudaEventRecord(eK2, s2);
    knn3_kernel<<<QPTS / 8, 256, 0, s2>>>(x, 3*QPTS);
    cudaEventRecord(eK3, s2);

    // s1: pre1 (full), kNN chunk 1
    pre1_kernel<<<(NPTS * 64) / 256, 256, 0, s1>>>(x, W1, b1);
    cudaEventRecord(eP1, s1);
    knn3_kernel<<<QPTS / 8, 256, 0, s1>>>(x, 1*QPTS);
    cudaEventRecord(eK1, s1);

    // main: kNN chunk 0, then ec1 backbone
    knn3_kernel<<<QPTS / 8, 256>>>(x, 0);
    cudaStreamWaitEvent(0, eP1, 0);
    ec1_kernel<<<QEDGE / 256, 256, EC1_SMEM>>>(W2, b2, W3, b3, 0);
    cudaEventRecord(eE0, 0);
    cudaStreamWaitEvent(0, eK1, 0);
    ec1_kernel<<<QEDGE / 256, 256, EC1_SMEM>>>(W2, b2, W3, b3, 1*QEDGE);
    cudaEventRecord(eE1, 0);
    cudaStreamWaitEvent(0, eK2, 0);
    ec1_kernel<<<QEDGE / 256, 256, EC1_SMEM>>>(W2, b2, W3, b3, 2*QEDGE);
    cudaEventRecord(eE2, 0);
    cudaStreamWaitEvent(0, eK3, 0);
    ec1_kernel<<<QEDGE / 256, 256, EC1_SMEM>>>(W2, b2, W3, b3, 3*QEDGE);

    // s1: tails 0 and 1
    cudaStreamWaitEvent(s1, eE0, 0);
    cudaStreamWaitEvent(s1, eZ, 0);
    norm64_kernel<<<QPTS / 256, 256, 0, s1>>>(0);
    dist64_kernel<<<dim3(36, QB), 256, D64_SMEM, s1>>>(0);
    topk_kernel<<<QPTS / 8, 256, 0, s1>>>(0);
    pre2_kernel<<<dim3(2, 64), 256, PRE2_SMEM, s1>>>(W4, b4, 0);
    ec2_kernel<<<QPTS, 128, 0, s1>>>(0);
    pool_kernel<<<dim3(64, 2), 512, POOL_SMEM, s1>>>(Wp, bp, 0);
    cudaStreamWaitEvent(s1, eE1, 0);
    norm64_kernel<<<QPTS / 256, 256, 0, s1>>>(1*QPTS);
    dist64_kernel<<<dim3(36, QB), 256, D64_SMEM, s1>>>(1*QB);
    topk_kernel<<<QPTS / 8, 256, 0, s1>>>(1*QPTS);
    pre2_kernel<<<dim3(2, 64), 256, PRE2_SMEM, s1>>>(W4, b4, 1*64);
    ec2_kernel<<<QPTS, 128, 0, s1>>>(1*QPTS);
    pool_kernel<<<dim3(64, 2), 512, POOL_SMEM, s1>>>(Wp, bp, 1*64);
    cudaEventRecord(eT01, s1);

    // s2: tail 2
    cudaStreamWaitEvent(s2, eE2, 0);
    cudaStreamWaitEvent(s2, eZ, 0);
    norm64_kernel<<<QPTS / 256, 256, 0, s2>>>(2*QPTS);
    dist64_kernel<<<dim3(36, QB), 256, D64_SMEM, s2>>>(2*QB);
    topk_kernel<<<QPTS / 8, 256, 0, s2>>>(2*QPTS);
    pre2_kernel<<<dim3(2, 64), 256, PRE2_SMEM, s2>>>(W4, b4, 2*64);
    ec2_kernel<<<QPTS, 128, 0, s2>>>(2*QPTS);
    pool_kernel<<<dim3(64, 2), 512, POOL_SMEM, s2>>>(Wp, bp, 2*64);
    cudaEventRecord(eT2, s2);

    // main: tail 3 (after ec1_3 on same stream)
    norm64_kernel<<<QPTS / 256, 256>>>(3*QPTS);
    dist64_kernel<<<dim3(36, QB), 256, D64_SMEM>>>(3*QB);
    topk_kernel<<<QPTS / 8, 256>>>(3*QPTS);
    pre2_kernel<<<dim3(2, 64), 256, PRE2_SMEM>>>(W4, b4, 3*64);
    ec2_kernel<<<QPTS, 128>>>(3*QPTS);
    cudaStreamWaitEvent(0, eZ, 0);
    pool_kernel<<<dim3(64, 2), 512, POOL_SMEM>>>(Wp, bp, 3*64);

    // join all tails, head
    cudaStreamWaitEvent(0, eT01, 0);
    cudaStreamWaitEvent(0, eT2, 0);
    head_kernel<<<BB, 256>>>(Wt1, bt1, Wt2, bt2, out);
}

// round 17
// speedup vs baseline: 1.0456x; 1.0456x over previous
#include <cuda_runtime.h>
#include <math_constants.h>

#define BB   32
#define NP   1024
#define KNN  20
#define NPTS (BB*NP)
#define NEDGE (NPTS*KNN)
#define HPTS (NPTS/2)
#define HEDGE (NEDGE/2)

// ---------------- scratch (device globals; no allocation allowed) ----------
__device__ float g_D[(size_t)BB*NP*NP];
__device__ int   g_idx[NPTS*KNN];
__device__ float g_p1[NPTS*64];
__device__ float g_q1[NPTS*64];
__device__ float g_f1[NPTS*64];
__device__ float g_norm[NPTS];
__device__ float g_p2[NPTS*128];
__device__ float g_q2[NPTS*128];
__device__ float g_f2[NPTS*128];
__device__ float g_pool[BB*512];

// monotonic u32 key for finite floats (never -0.0 here)
__device__ __forceinline__ unsigned monokey(float f) {
    unsigned u = __float_as_uint(f);
    return (u & 0x80000000u) ? ~u : (u | 0x80000000u);
}

// ---------------- 1) fused kNN on xyz: REDUX + top-2 cached selection ------
__global__ void __launch_bounds__(256) knn3_kernel(const float* __restrict__ x, int rb0) {
    __shared__ float sx[NP], sy[NP], sz[NP], sq[NP];
    int rowBase = rb0 + blockIdx.x * 8;
    int b = rowBase >> 10;
    const float* xb = x + (size_t)b * NP * 3;
    for (int i = threadIdx.x; i < NP; i += 256) {
        float a0 = xb[i*3], a1 = xb[i*3+1], a2 = xb[i*3+2];
        sx[i] = a0; sy[i] = a1; sz[i] = a2;
        sq[i] = a0*a0 + a1*a1 + a2*a2;
    }
    __syncthreads();
    int warp = threadIdx.x >> 5, lane = threadIdx.x & 31;
    int n  = rowBase + warp;
    int nl = n & (NP - 1);
    float qx = sx[nl], qy = sy[nl], qz = sz[nl], qs = sq[nl];
    float v[32];
#pragma unroll
    for (int i = 0; i < 32; i++) {
        int m = lane + (i << 5);
        float d = qs + sq[m] - 2.0f * (qx*sx[m] + qy*sy[m] + qz*sz[m]);
        v[i] = (m == nl) ? CUDART_INF_F : d;
    }
    float bv = v[0]; int bi = 0;
    float bv2 = CUDART_INF_F; int bi2 = -1;
#pragma unroll
    for (int i = 1; i < 32; i++) {
        float vi = v[i];
        if (vi < bv)       { bv2 = bv; bi2 = bi; bv = vi; bi = i; }
        else if (vi < bv2) { bv2 = vi; bi2 = i; }
    }
    unsigned popped = 0u;
    for (int r = 0; r < KNN; r++) {
        unsigned key = monokey(bv);
        unsigned rm  = __reduce_min_sync(0xffffffffu, key);
        unsigned myg = (unsigned)((bi << 5) | lane);
        unsigned cand = (key == rm) ? myg : 0xffffffffu;
        unsigned mi = __reduce_min_sync(0xffffffffu, cand);
        if (lane == 0) g_idx[n * KNN + r] = (int)mi;
        if (mi == myg) {
            popped |= 1u << bi;
            if (bi2 >= 0) { bv = bv2; bi = bi2; bi2 = -1; }
            else {
                bv = CUDART_INF_F; bi = 0; bv2 = CUDART_INF_F; bi2 = -1;
#pragma unroll
                for (int i = 0; i < 32; i++) {
                    if (popped & (1u << i)) continue;
                    float vi = v[i];
                    if (vi < bv)       { bv2 = bv; bi2 = bi; bv = vi; bi = i; }
                    else if (vi < bv2) { bv2 = vi; bi2 = i; }
                }
            }
        }
    }
}

// ---------------- 2) top-20 per row of g_D: same selection, float4 loads ----
__global__ void topk_kernel(int rb0) {
    int row  = rb0 + blockIdx.x * 8 + (threadIdx.x >> 5);
    int lane = threadIdx.x & 31;
    int nl = row & (NP - 1);
    const float* d = g_D + (size_t)row * NP;
    float v[32];
#pragma unroll
    for (int g = 0; g < 8; g++) {
        int base = g * 128 + lane * 4;
        float4 t4 = *(const float4*)(d + base);
        v[g*4+0] = (base + 0 == nl) ? CUDART_INF_F : t4.x;
        v[g*4+1] = (base + 1 == nl) ? CUDART_INF_F : t4.y;
        v[g*4+2] = (base + 2 == nl) ? CUDART_INF_F : t4.z;
        v[g*4+3] = (base + 3 == nl) ? CUDART_INF_F : t4.w;
    }
    float bv = v[0]; int bi = 0;
    float bv2 = CUDART_INF_F; int bi2 = -1;
#pragma unroll
    for (int i = 1; i < 32; i++) {
        float vi = v[i];
        if (vi < bv)       { bv2 = bv; bi2 = bi; bv = vi; bi = i; }
        else if (vi < bv2) { bv2 = vi; bi2 = i; }
    }
    unsigned popped = 0u;
    for (int r = 0; r < KNN; r++) {
        unsigned key = monokey(bv);
        unsigned rm  = __reduce_min_sync(0xffffffffu, key);
        unsigned myg = (unsigned)(((bi >> 2) << 7) | (lane << 2) | (bi & 3));
        unsigned cand = (key == rm) ? myg : 0xffffffffu;
        unsigned mi = __reduce_min_sync(0xffffffffu, cand);
        if (lane == 0) g_idx[row * KNN + r] = (int)mi;
        if (mi == myg) {
            popped |= 1u << bi;
            if (bi2 >= 0) { bv = bv2; bi = bi2; bi2 = -1; }
            else {
                bv = CUDART_INF_F; bi = 0; bv2 = CUDART_INF_F; bi2 = -1;
#pragma unroll
                for (int i = 0; i < 32; i++) {
                    if (popped & (1u << i)) continue;
                    float vi = v[i];
                    if (vi < bv)       { bv2 = bv; bi2 = bi; bv = vi; bi = i; }
                    else if (vi < bv2) { bv2 = vi; bi2 = i; }
                }
            }
        }
    }
}

// ---------------- 3) EdgeConv1 layer-1 split precompute (+ zero f1) --------
__global__ void pre1_kernel(const float* __restrict__ x,
                            const float* __restrict__ W1,
                            const float* __restrict__ b1) {
    int id = blockIdx.x * blockDim.x + threadIdx.x;
    if (id >= NPTS * 64) return;
    int n = id >> 6, t = id & 63;
    float x0 = x[n*3], x1 = x[n*3+1], x2 = x[n*3+2];
    float wa0 = W1[t],       wa1 = W1[64 + t],  wa2 = W1[128 + t];
    float wb0 = W1[192 + t], wb1 = W1[256 + t], wb2 = W1[320 + t];
    float q = x0*wb0 + x1*wb1 + x2*wb2;
    float p = b1[t] + x0*(wa0-wb0) + x1*(wa1-wb1) + x2*(wa2-wb2);
    g_p1[id] = p;
    g_q1[id] = q;
    g_f1[id] = 0.0f;
}

// ---------------- 4) EdgeConv1: interleaved channel cols (bank-conflict-free)
#define ETP 260
#define EC1_SMEM ((64*ETP + 4096 + 4096 + 64 + 64) * 4)
__global__ void __launch_bounds__(256, 2) ec1_kernel(const float* __restrict__ W2,
                                                     const float* __restrict__ b2,
                                                     const float* __restrict__ W3,
                                                     const float* __restrict__ b3,
                                                     int eb0) {
    extern __shared__ float sm[];
    float* ET  = sm;
    float* sW2 = sm + 64*ETP;
    float* sW3 = sW2 + 4096;
    float* sB2 = sW3 + 4096;
    float* sB3 = sB2 + 64;
    int tid = threadIdx.x;
    int tx = tid & 7, ty = tid >> 3;   // edges ty*8..+7; channels tx*4..+3 and 32+tx*4..+3

    for (int i = tid; i < 4096; i += 256) { sW2[i] = W2[i]; sW3[i] = W3[i]; }
    if (tid < 64) { sB2[tid] = b2[tid]; sB3[tid] = b3[tid]; }

    int B0 = eb0 + blockIdx.x * 256;
    int g  = B0 + tid;
    int p  = g / KNN;
    int b  = p >> 10;
    int j  = g_idx[g];
    const float* pr = g_p1 + (size_t)p * 64;
    const float* qr = g_q1 + ((size_t)(b << 10) + j) * 64;
    __syncthreads();
#pragma unroll
    for (int c = 0; c < 64; c += 4) {
        float4 pv = *(const float4*)(pr + c);
        float4 qv = *(const float4*)(qr + c);
        ET[(c+0)*ETP + tid] = fmaxf(pv.x + qv.x, 0.0f);
        ET[(c+1)*ETP + tid] = fmaxf(pv.y + qv.y, 0.0f);
        ET[(c+2)*ETP + tid] = fmaxf(pv.z + qv.z, 0.0f);
        ET[(c+3)*ETP + tid] = fmaxf(pv.w + qv.w, 0.0f);
    }
    __syncthreads();

    float acc[8][8];
    // ---- layer 2: H = relu(E @ W2 + b2) ----
#pragma unroll
    for (int i = 0; i < 8; i++)
#pragma unroll
        for (int jj = 0; jj < 8; jj++) acc[i][jj] = 0.0f;
#pragma unroll 4
    for (int k = 0; k < 64; k++) {
        float4 a0 = *(const float4*)(ET + k*ETP + ty*8);
        float4 a1 = *(const float4*)(ET + k*ETP + ty*8 + 4);
        float4 w0 = *(const float4*)(sW2 + k*64 + tx*4);        // chans tx*4..+3
        float4 w1 = *(const float4*)(sW2 + k*64 + 32 + tx*4);   // chans 32+tx*4..+3
        float a[8] = {a0.x,a0.y,a0.z,a0.w,a1.x,a1.y,a1.z,a1.w};
        float w[8] = {w0.x,w0.y,w0.z,w0.w,w1.x,w1.y,w1.z,w1.w};
#pragma unroll
        for (int i = 0; i < 8; i++)
#pragma unroll
            for (int jj = 0; jj < 8; jj++) acc[i][jj] = fmaf(a[i], w[jj], acc[i][jj]);
    }
    float bv2[8], bv3[8];
#pragma unroll
    for (int jj = 0; jj < 8; jj++) {
        int ch = (jj < 4) ? (tx*4 + jj) : (32 + tx*4 + (jj - 4));
        bv2[jj] = sB2[ch]; bv3[jj] = sB3[ch];
    }
    __syncthreads();
    // store H^T (channel-major), interleaved channel ownership
#pragma unroll
    for (int jj = 0; jj < 8; jj++) {
        int ch = (jj < 4) ? (tx*4 + jj) : (32 + tx*4 + (jj - 4));
#pragma unroll
        for (int i = 0; i < 8; i++)
            ET[ch*ETP + ty*8 + i] = fmaxf(acc[i][jj] + bv2[jj], 0.0f);
    }
    __syncthreads();

    // ---- layer 3: out = H @ W3 + b3 ----
#pragma unroll
    for (int i = 0; i < 8; i++)
#pragma unroll
        for (int jj = 0; jj < 8; jj++) acc[i][jj] = 0.0f;
#pragma unroll 4
    for (int k = 0; k < 64; k++) {
        float4 a0 = *(const float4*)(ET + k*ETP + ty*8);
        float4 a1 = *(const float4*)(ET + k*ETP + ty*8 + 4);
        float4 w0 = *(const float4*)(sW3 + k*64 + tx*4);
        float4 w1 = *(const float4*)(sW3 + k*64 + 32 + tx*4);
        float a[8] = {a0.x,a0.y,a0.z,a0.w,a1.x,a1.y,a1.z,a1.w};
        float w[8] = {w0.x,w0.y,w0.z,w0.w,w1.x,w1.y,w1.z,w1.w};
#pragma unroll
        for (int i = 0; i < 8; i++)
#pragma unroll
            for (int jj = 0; jj < 8; jj++) acc[i][jj] = fmaf(a[i], w[jj], acc[i][jj]);
    }
    __syncthreads();                   // reuse ET as OUT[256][64]
#pragma unroll
    for (int i = 0; i < 8; i++) {
        float4 v0, v1;
        v0.x = acc[i][0] + bv3[0]; v0.y = acc[i][1] + bv3[1];
        v0.z = acc[i][2] + bv3[2]; v0.w = acc[i][3] + bv3[3];
        v1.x = acc[i][4] + bv3[4]; v1.y = acc[i][5] + bv3[5];
        v1.z = acc[i][6] + bv3[6]; v1.w = acc[i][7] + bv3[7];
        *(float4*)(ET + (ty*8+i)*64 + tx*4)      = v0;   // chans tx*4..+3
        *(float4*)(ET + (ty*8+i)*64 + 32 + tx*4) = v1;   // chans 32+tx*4..+3
    }
    __syncthreads();

    int pFirst = B0 / KNN;
    int pLast  = (B0 + 255) / KNN;
    int nseg   = pLast - pFirst + 1;
    int ch = tid & 63;
    for (int s = tid >> 6; s < nseg; s += 4) {
        int pt = pFirst + s;
        int r0 = max(pt * KNN,       B0) - B0;
        int r1 = min(pt * KNN + KNN, B0 + 256) - B0;
        if (r0 >= r1) continue;
        float m = ET[r0*64 + ch];
        for (int r = r0 + 1; r < r1; r++) m = fmaxf(m, ET[r*64 + ch]);
        atomicMax((int*)&g_f1[(size_t)pt*64 + ch], __float_as_int(m));
    }
}

// ---------------- 4b) squared norms of f1 rows (point offset) ---------------
__global__ void norm64_kernel(int nb0) {
    int n = nb0 + blockIdx.x * 256 + threadIdx.x;
    const float4* r = (const float4*)(g_f1 + (size_t)n * 64);
    float s = 0.0f;
#pragma unroll
    for (int i = 0; i < 16; i++) {
        float4 v = r[i];
        s += v.x*v.x + v.y*v.y + v.z*v.z + v.w*v.w;
    }
    g_norm[n] = s;
}

// ---------------- 5) dist64: SYMMETRIC Gram GEMM (batch offset) -------------
#define TS 132
#define D64_SMEM ((32*TS*2 + 256) * 4)
__global__ void __launch_bounds__(256) dist64_kernel(int bb0) {
    extern __shared__ float sm[];
    float* sAt = sm;
    float* sBt = sm + 32*TS;
    float* snA = sm + 64*TS;
    float* snB = snA + 128;
    int b = bb0 + blockIdx.y;
    int t = blockIdx.x, ti = 0;
    while (t >= 8 - ti) { t -= 8 - ti; ti++; }
    int tj = ti + t;
    int m0 = ti * 128, n0 = tj * 128;
    int tid = threadIdx.x;
    int tx = tid & 15, ty = tid >> 4;
    const float* F = g_f1 + (size_t)b * NP * 64;

    if (tid < 128)      snA[tid]       = g_norm[b*NP + m0 + tid];
    else                snB[tid - 128] = g_norm[b*NP + n0 + tid - 128];

    float acc[8][8];
#pragma unroll
    for (int i = 0; i < 8; i++)
#pragma unroll
        for (int j = 0; j < 8; j++) acc[i][j] = 0.0f;

    for (int kc = 0; kc < 2; kc++) {
        __syncthreads();
#pragma unroll
        for (int l = 0; l < 16; l++) {
            int idx = l * 256 + tid;
            int r = idx >> 5, c = idx & 31;
            sAt[c * TS + r] = F[(size_t)(m0 + r) * 64 + kc * 32 + c];
            sBt[c * TS + r] = F[(size_t)(n0 + r) * 64 + kc * 32 + c];
        }
        __syncthreads();
        for (int k = 0; k < 32; k++) {
            float4 a0 = *(const float4*)(sAt + k * TS + ty * 8);
            float4 a1 = *(const float4*)(sAt + k * TS + ty * 8 + 4);
            float4 c0 = *(const float4*)(sBt + k * TS + tx * 4);
            float4 c1 = *(const float4*)(sBt + k * TS + 64 + tx * 4);
            float a[8]  = {a0.x, a0.y, a0.z, a0.w, a1.x, a1.y, a1.z, a1.w};
            float bv[8] = {c0.x, c0.y, c0.z, c0.w, c1.x, c1.y, c1.z, c1.w};
#pragma unroll
            for (int i = 0; i < 8; i++)
#pragma unroll
                for (int j = 0; j < 8; j++) acc[i][j] = fmaf(a[i], bv[j], acc[i][j]);
        }
    }
    float* Dp = g_D + (size_t)b * NP * NP;
    float nb_[8];
#pragma unroll
    for (int j = 0; j < 8; j++) nb_[j] = (j < 4) ? snB[tx*4 + j] : snB[64 + tx*4 + (j-4)];

    float dv[8][8];
#pragma unroll
    for (int i = 0; i < 8; i++) {
        float nai = snA[ty*8 + i];
#pragma unroll
        for (int j = 0; j < 8; j++) dv[i][j] = nai + nb_[j] - 2.0f * acc[i][j];
    }
#pragma unroll
    for (int i = 0; i < 8; i++) {
        float* row = Dp + (size_t)(m0 + ty*8 + i) * NP;
        *(float4*)(row + n0 + tx*4)      = make_float4(dv[i][0], dv[i][1], dv[i][2], dv[i][3]);
        *(float4*)(row + n0 + 64 + tx*4) = make_float4(dv[i][4], dv[i][5], dv[i][6], dv[i][7]);
    }
    if (ti != tj) {
#pragma unroll
        for (int j = 0; j < 8; j++) {
            int cl = (j < 4) ? (tx*4 + j) : (64 + tx*4 + (j-4));
            float* row = Dp + (size_t)(n0 + cl) * NP + m0 + ty*8;
            *(float4*)row       = make_float4(dv[0][j], dv[1][j], dv[2][j], dv[3][j]);
            *(float4*)(row + 4) = make_float4(dv[4][j], dv[5][j], dv[6][j], dv[7][j]);
        }
    }
}

// ---------------- 6) pre2 as GEMM (m-tile offset) ---------------------------
#define PRE2_SMEM ((32*TS*2 + 128) * 4)
__global__ void __launch_bounds__(256) pre2_kernel(const float* __restrict__ W4,
                                                   const float* __restrict__ b4,
                                                   int mt0) {
    extern __shared__ float sm[];
    float* sAt = sm;
    float* sBt = sm + 32*TS;
    float* sBias = sm + 64*TS;
    int nblk = blockIdx.x;
    int m0 = (mt0 + blockIdx.y) * 128;
    int tid = threadIdx.x;
    int tx = tid & 15, ty = tid >> 4;

    if (tid < 128) sBias[tid] = (nblk == 0) ? b4[tid] : 0.0f;

    float acc[8][8];
#pragma unroll
    for (int i = 0; i < 8; i++)
#pragma unroll
        for (int j = 0; j < 8; j++) acc[i][j] = 0.0f;

    for (int kc = 0; kc < 2; kc++) {
        __syncthreads();
#pragma unroll
        for (int l = 0; l < 16; l++) {
            int idx = l * 256 + tid;
            int r = idx >> 5, c = idx & 31;
            sAt[c * TS + r] = g_f1[(size_t)(m0 + r) * 64 + kc * 32 + c];
        }
#pragma unroll
        for (int l = 0; l < 16; l++) {
            int idx = l * 256 + tid;
            int nl = idx & 127, kk = idx >> 7;
            int k = kc * 32 + kk;
            float wb = W4[(64 + k) * 128 + nl];
            float w  = (nblk == 0) ? (W4[k * 128 + nl] - wb) : wb;
            sBt[kk * TS + nl] = w;
        }
        __syncthreads();
        for (int k = 0; k < 32; k++) {
            float4 a0 = *(const float4*)(sAt + k * TS + ty * 8);
            float4 a1 = *(const float4*)(sAt + k * TS + ty * 8 + 4);
            float4 c0 = *(const float4*)(sBt + k * TS + tx * 8);
            float4 c1 = *(const float4*)(sBt + k * TS + tx * 8 + 4);
            float a[8]  = {a0.x, a0.y, a0.z, a0.w, a1.x, a1.y, a1.z, a1.w};
            float bv[8] = {c0.x, c0.y, c0.z, c0.w, c1.x, c1.y, c1.z, c1.w};
#pragma unroll
            for (int i = 0; i < 8; i++)
#pragma unroll
                for (int j = 0; j < 8; j++) acc[i][j] = fmaf(a[i], bv[j], acc[i][j]);
        }
    }
    float* dst = (nblk == 0) ? g_p2 : g_q2;
    float bb[8];
#pragma unroll
    for (int j = 0; j < 8; j++) bb[j] = sBias[tx*8 + j];
#pragma unroll
    for (int i = 0; i < 8; i++) {
        float4 o0, o1;
        o0.x = acc[i][0] + bb[0]; o0.y = acc[i][1] + bb[1];
        o0.z = acc[i][2] + bb[2]; o0.w = acc[i][3] + bb[3];
        o1.x = acc[i][4] + bb[4]; o1.y = acc[i][5] + bb[5];
        o1.z = acc[i][6] + bb[6]; o1.w = acc[i][7] + bb[7];
        float* row = dst + (size_t)(m0 + ty*8 + i) * 128 + tx*8;
        *(float4*)row       = o0;
        *(float4*)(row + 4) = o1;
    }
}

// ---------------- 7) EdgeConv2: max_k relu(p + q) (point offset) ------------
__global__ void ec2_kernel(int nb0) {
    int n = nb0 + blockIdx.x, t = threadIdx.x;
    int b = n >> 10;
    float p = g_p2[(size_t)n * 128 + t];
    const int* idxp = g_idx + n * KNN;
    float best = 0.0f;
#pragma unroll
    for (int k = 0; k < KNN; k++) {
        int j = idxp[k];
        float q = g_q2[((size_t)(b << 10) + j) * 128 + t];
        best = fmaxf(best, p + q);
    }
    g_f2[(size_t)n * 128 + t] = best;
}

// ---------------- 8) pool: 128x256 tiles (m-tile offset) --------------------
__global__ void zero_pool_kernel() {
    int i = blockIdx.x * blockDim.x + threadIdx.x;
    if (i < BB * 512) g_pool[i] = 0.0f;
}

#define POOLN 260
#define POOL_SMEM ((32*TS + 32*POOLN + 16*256) * 4)
__global__ void __launch_bounds__(512) pool_kernel(const float* __restrict__ Wp,
                                                   const float* __restrict__ bp,
                                                   int mt0) {
    extern __shared__ float smp[];
    float* sAt  = smp;
    float* sBt  = smp + 32*TS;
    float* sred = smp + 32*TS + 32*POOLN;
    int m0 = (mt0 + blockIdx.x) * 128, n0 = blockIdx.y * 256;
    int b  = m0 >> 10;
    int tid = threadIdx.x;
    int tx = tid & 31, ty = tid >> 5;

    float acc[8][8];
#pragma unroll
    for (int i = 0; i < 8; i++)
#pragma unroll
        for (int j = 0; j < 8; j++) acc[i][j] = 0.0f;

    for (int kc = 0; kc < 4; kc++) {
        __syncthreads();
#pragma unroll
        for (int l = 0; l < 8; l++) {
            int idx = l * 512 + tid;
            int r = idx >> 5, c = idx & 31;
            sAt[c * TS + r] = g_f2[(size_t)(m0 + r) * 128 + kc * 32 + c];
        }
#pragma unroll
        for (int l = 0; l < 16; l++) {
            int idx = l * 512 + tid;
            int nn = idx & 255, kk = idx >> 8;
            sBt[kk * POOLN + nn] = Wp[(size_t)(kc * 32 + kk) * 512 + n0 + nn];
        }
        __syncthreads();
        for (int k = 0; k < 32; k++) {
            float4 a0 = *(const float4*)(sAt + k * TS + ty * 8);
            float4 a1 = *(const float4*)(sAt + k * TS + ty * 8 + 4);
            float4 c0 = *(const float4*)(sBt + k * POOLN + tx * 8);
            float4 c1 = *(const float4*)(sBt + k * POOLN + tx * 8 + 4);
            float a[8]  = {a0.x, a0.y, a0.z, a0.w, a1.x, a1.y, a1.z, a1.w};
            float bv[8] = {c0.x, c0.y, c0.z, c0.w, c1.x, c1.y, c1.z, c1.w};
#pragma unroll
            for (int i = 0; i < 8; i++)
#pragma unroll
                for (int j = 0; j < 8; j++) acc[i][j] = fmaf(a[i], bv[j], acc[i][j]);
        }
    }
#pragma unroll
    for (int j = 0; j < 8; j++) {
        int col = n0 + tx * 8 + j;
        float bpv = bp[col];
        float cm = 0.0f;
#pragma unroll
        for (int i = 0; i < 8; i++) cm = fmaxf(cm, acc[i][j] + bpv);
        sred[ty * 256 + tx * 8 + j] = cm;
    }
    __syncthreads();
    if (ty == 0) {
#pragma unroll
        for (int j = 0; j < 8; j++) {
            int c = tx * 8 + j;
            float cm = 0.0f;
#pragma unroll
            for (int yy = 0; yy < 16; yy++) cm = fmaxf(cm, sred[yy * 256 + c]);
            atomicMax((int*)&g_pool[b * 512 + n0 + c], __float_as_int(cm));
        }
    }
}

// ---------------- 9) classifier head ----------------------------------------
__global__ void head_kernel(const float* __restrict__ Wt1, const float* __restrict__ bt1,
                            const float* __restrict__ Wt2, const float* __restrict__ bt2,
                            float* __restrict__ out) {
    __shared__ float sp[512];
    __shared__ float st[256];
    int b = blockIdx.x, t = threadIdx.x;
    sp[t]       = g_pool[b * 512 + t];
    sp[256 + t] = g_pool[b * 512 + 256 + t];
    __syncthreads();
    float acc = bt1[t];
#pragma unroll 8
    for (int c = 0; c < 512; c++) acc = fmaf(sp[c], Wt1[c * 256 + t], acc);
    st[t] = fmaxf(acc, 0.0f);
    __syncthreads();
    if (t < 40) {
        float a2 = bt2[t];
#pragma unroll 8
        for (int c = 0; c < 256; c++) a2 = fmaf(st[c], Wt2[c * 40 + t], a2);
        out[b * 40 + t] = a2;
    }
}

// ---------------- launch: batch-halved 2-stage pipeline (R15 schedule) ------
extern "C" void kernel_launch(void* const* d_in, const int* in_sizes, int n_in,
                              void* d_out, int out_size) {
    const float* x   = (const float*)d_in[0];
    const float* W1  = (const float*)d_in[2];
    const float* b1  = (const float*)d_in[3];
    const float* W2  = (const float*)d_in[4];
    const float* b2  = (const float*)d_in[5];
    const float* W3  = (const float*)d_in[6];
    const float* b3  = (const float*)d_in[7];
    const float* W4  = (const float*)d_in[8];
    const float* b4  = (const float*)d_in[9];
    const float* Wp  = (const float*)d_in[10];
    const float* bp  = (const float*)d_in[11];
    const float* Wt1 = (const float*)d_in[12];
    const float* bt1 = (const float*)d_in[13];
    const float* Wt2 = (const float*)d_in[14];
    const float* bt2 = (const float*)d_in[15];
    float* out = (float*)d_out;

    static cudaStream_t s1 = nullptr, s2 = nullptr;
    static cudaEvent_t eR = nullptr, eP1 = nullptr, eKB = nullptr,
                       eA1 = nullptr, eZ = nullptr, ePA = nullptr;
    if (s1 == nullptr) {
        cudaStreamCreateWithFlags(&s1, cudaStreamNonBlocking);
        cudaStreamCreateWithFlags(&s2, cudaStreamNonBlocking);
        cudaEventCreateWithFlags(&eR,  cudaEventDisableTiming);
        cudaEventCreateWithFlags(&eP1, cudaEventDisableTiming);
        cudaEventCreateWithFlags(&eKB, cudaEventDisableTiming);
        cudaEventCreateWithFlags(&eA1, cudaEventDisableTiming);
        cudaEventCreateWithFlags(&eZ,  cudaEventDisableTiming);
        cudaEventCreateWithFlags(&ePA, cudaEventDisableTiming);
        cudaFuncSetAttribute(ec1_kernel,    cudaFuncAttributeMaxDynamicSharedMemorySize, EC1_SMEM);
        cudaFuncSetAttribute(dist64_kernel, cudaFuncAttributeMaxDynamicSharedMemorySize, D64_SMEM);
        cudaFuncSetAttribute(pre2_kernel,   cudaFuncAttributeMaxDynamicSharedMemorySize, PRE2_SMEM);
        cudaFuncSetAttribute(pool_kernel,   cudaFuncAttributeMaxDynamicSharedMemorySize, POOL_SMEM);
    }

    cudaEventRecord(eR, 0);
    cudaStreamWaitEvent(s1, eR, 0);
    cudaStreamWaitEvent(s2, eR, 0);

    // s2: zero pool, then kNN for half B
    zero_pool_kernel<<<16, 1024, 0, s2>>>();
    cudaEventRecord(eZ, s2);
    knn3_kernel<<<HPTS / 8, 256, 0, s2>>>(x, HPTS);
    cudaEventRecord(eKB, s2);

    // s1: pre1 (full)
    pre1_kernel<<<(NPTS * 64) / 256, 256, 0, s1>>>(x, W1, b1);
    cudaEventRecord(eP1, s1);

    // main: kNN half A, then ec1 half A
    knn3_kernel<<<HPTS / 8, 256>>>(x, 0);
    cudaStreamWaitEvent(0, eP1, 0);
    ec1_kernel<<<HEDGE / 256, 256, EC1_SMEM>>>(W2, b2, W3, b3, 0);
    cudaEventRecord(eA1, 0);

    // s1: full A-tail (overlaps ec1_B + B-tail on main)
    cudaStreamWaitEvent(s1, eA1, 0);
    norm64_kernel<<<HPTS / 256, 256, 0, s1>>>(0);
    dist64_kernel<<<dim3(36, BB/2), 256, D64_SMEM, s1>>>(0);
    topk_kernel<<<HPTS / 8, 256, 0, s1>>>(0);
    pre2_kernel<<<dim3(2, 128), 256, PRE2_SMEM, s1>>>(W4, b4, 0);
    ec2_kernel<<<HPTS, 128, 0, s1>>>(0);
    cudaStreamWaitEvent(s1, eZ, 0);
    pool_kernel<<<dim3(128, 2), 512, POOL_SMEM, s1>>>(Wp, bp, 0);
    cudaEventRecord(ePA, s1);

    // main: ec1 half B + full B-tail
    cudaStreamWaitEvent(0, eKB, 0);
    ec1_kernel<<<HEDGE / 256, 256, EC1_SMEM>>>(W2, b2, W3, b3, HEDGE);
    norm64_kernel<<<HPTS / 256, 256>>>(HPTS);
    dist64_kernel<<<dim3(36, BB/2), 256, D64_SMEM>>>(BB/2);
    topk_kernel<<<HPTS / 8, 256>>>(HPTS);
    pre2_kernel<<<dim3(2, 128), 256, PRE2_SMEM>>>(W4, b4, 128);
    ec2_kernel<<<HPTS, 128>>>(HPTS);
    cudaStreamWaitEvent(0, eZ, 0);
    pool_kernel<<<dim3(128, 2), 512, POOL_SMEM>>>(Wp, bp, 128);

    // join A-tail, head
    cudaStreamWaitEvent(0, ePA, 0);
    head_kernel<<<BB, 256>>>(Wt1, bt1, Wt2, bt2, out);
}